// round 4
// baseline (speedup 1.0000x reference)
#include <cuda_runtime.h>

// GraphAttentionPooling: B=32, N=3072, F=256, P=3 -> S=1024, 32768 windows.
// Persistent exact-fit grid (148 SMs x 2 blocks x 8 warps = 2368 warps).
// Each warp processes 2 consecutive windows per iteration with depth-1
// software prefetch -> 12 LDG.128 in flight per warp during the compute chain.
// Lane l owns features [8l, 8l+8) as 2x float4. Streaming loads/stores (.cs).

#define F_DIM 256
#define P_DIM 3
#define NUM_SMS 148
#define BLOCKS_PER_SM 2
#define THREADS_PER_BLOCK 256

__device__ __forceinline__ float warp_reduce_sum(float v) {
    #pragma unroll
    for (int off = 16; off > 0; off >>= 1)
        v += __shfl_xor_sync(0xFFFFFFFFu, v, off);
    return v;
}

__device__ __forceinline__ float dot8(float4 a, float4 b, float4 wa, float4 wb) {
    float s = a.x * wa.x;
    s = fmaf(a.y, wa.y, s);
    s = fmaf(a.z, wa.z, s);
    s = fmaf(a.w, wa.w, s);
    s = fmaf(b.x, wb.x, s);
    s = fmaf(b.y, wb.y, s);
    s = fmaf(b.z, wb.z, s);
    s = fmaf(b.w, wb.w, s);
    return s;
}

// Softmax over 3 + weighted combine for one window held as 6 float4.
__device__ __forceinline__ void combine_store(
    float s0, float s1, float s2,
    float4 r0a, float4 r0b, float4 r1a, float4 r1b, float4 r2a, float4 r2b,
    float4* o)
{
    float m = fmaxf(s0, fmaxf(s1, s2));
    float e0 = __expf(s0 - m);
    float e1 = __expf(s1 - m);
    float e2 = __expf(s2 - m);
    float inv = 1.0f / (e0 + e1 + e2);
    float a0 = e0 * inv, a1 = e1 * inv, a2 = e2 * inv;

    float4 oa, ob;
    oa.x = fmaf(r2a.x, a2, fmaf(r1a.x, a1, r0a.x * a0));
    oa.y = fmaf(r2a.y, a2, fmaf(r1a.y, a1, r0a.y * a0));
    oa.z = fmaf(r2a.z, a2, fmaf(r1a.z, a1, r0a.z * a0));
    oa.w = fmaf(r2a.w, a2, fmaf(r1a.w, a1, r0a.w * a0));
    ob.x = fmaf(r2b.x, a2, fmaf(r1b.x, a1, r0b.x * a0));
    ob.y = fmaf(r2b.y, a2, fmaf(r1b.y, a1, r0b.y * a0));
    ob.z = fmaf(r2b.z, a2, fmaf(r1b.z, a1, r0b.z * a0));
    ob.w = fmaf(r2b.w, a2, fmaf(r1b.w, a1, r0b.w * a0));

    __stcs(o,     oa);
    __stcs(o + 1, ob);
}

__global__ void __launch_bounds__(THREADS_PER_BLOCK, BLOCKS_PER_SM)
gap_kernel(const float* __restrict__ x,
           const float* __restrict__ Ww,
           const float* __restrict__ Wb,
           float* __restrict__ out,
           int n_pairs) {
    const int warp_id = (blockIdx.x * blockDim.x + threadIdx.x) >> 5;
    const int lane    = threadIdx.x & 31;
    const int n_warps = (int)((gridDim.x * blockDim.x) >> 5);

    const int fv = lane * 2;  // float4 index within a row (row = 64 float4)

    const float4* Wv = reinterpret_cast<const float4*>(Ww);
    const float4 wa = Wv[fv], wb = Wv[fv + 1];
    const float bias = Wb[0];

    const float4* xbase = reinterpret_cast<const float4*>(x);
    float4*       obase = reinterpret_cast<float4*>(out);

    int p = warp_id;
    if (p >= n_pairs) return;

    // Pair stride: 2 windows * 192 float4 = 384 float4 (6 KB).
    const float4* xp = xbase + (long long)p * 384 + fv;
    // Window A rows at 0,64,128; window B rows at 192,256,320.
    float4 nA0a = __ldcs(xp +   0), nA0b = __ldcs(xp +   1);
    float4 nA1a = __ldcs(xp +  64), nA1b = __ldcs(xp +  65);
    float4 nA2a = __ldcs(xp + 128), nA2b = __ldcs(xp + 129);
    float4 nB0a = __ldcs(xp + 192), nB0b = __ldcs(xp + 193);
    float4 nB1a = __ldcs(xp + 256), nB1b = __ldcs(xp + 257);
    float4 nB2a = __ldcs(xp + 320), nB2b = __ldcs(xp + 321);

    for (; p < n_pairs; p += n_warps) {
        // Current pair = last prefetch.
        float4 A0a = nA0a, A0b = nA0b, A1a = nA1a, A1b = nA1b, A2a = nA2a, A2b = nA2b;
        float4 B0a = nB0a, B0b = nB0b, B1a = nB1a, B1b = nB1b, B2a = nB2a, B2b = nB2b;

        // Prefetch next pair BEFORE the dependent compute chain (clamped index,
        // warp-uniform; final iteration reloads self -> L2 hit, harmless).
        {
            int pn = p + n_warps;
            pn = (pn < n_pairs) ? pn : p;
            const float4* nx = xbase + (long long)pn * 384 + fv;
            nA0a = __ldcs(nx +   0); nA0b = __ldcs(nx +   1);
            nA1a = __ldcs(nx +  64); nA1b = __ldcs(nx +  65);
            nA2a = __ldcs(nx + 128); nA2b = __ldcs(nx + 129);
            nB0a = __ldcs(nx + 192); nB0b = __ldcs(nx + 193);
            nB1a = __ldcs(nx + 256); nB1b = __ldcs(nx + 257);
            nB2a = __ldcs(nx + 320); nB2b = __ldcs(nx + 321);
        }

        // Six independent butterfly reductions (2 windows x 3 rows) — ILP.
        float sA0 = warp_reduce_sum(dot8(A0a, A0b, wa, wb)) + bias;
        float sA1 = warp_reduce_sum(dot8(A1a, A1b, wa, wb)) + bias;
        float sA2 = warp_reduce_sum(dot8(A2a, A2b, wa, wb)) + bias;
        float sB0 = warp_reduce_sum(dot8(B0a, B0b, wa, wb)) + bias;
        float sB1 = warp_reduce_sum(dot8(B1a, B1b, wa, wb)) + bias;
        float sB2 = warp_reduce_sum(dot8(B2a, B2b, wa, wb)) + bias;

        float4* o = obase + (long long)p * 128 + fv;  // 2 windows * 64 float4
        combine_store(sA0, sA1, sA2, A0a, A0b, A1a, A1b, A2a, A2b, o);
        combine_store(sB0, sB1, sB2, B0a, B0b, B1a, B1b, B2a, B2b, o + 64);
    }
}

extern "C" void kernel_launch(void* const* d_in, const int* in_sizes, int n_in,
                              void* d_out, int out_size) {
    const float* x  = (const float*)d_in[0];  // [32, 3072, 256]
    const float* Ww = (const float*)d_in[1];  // [256]
    const float* Wb = (const float*)d_in[2];  // [1]
    float* out = (float*)d_out;               // [32, 1024, 256, 1]

    const int n_windows = in_sizes[0] / (P_DIM * F_DIM);  // 32768
    const int n_pairs   = n_windows / 2;                  // 16384
    const int blocks    = NUM_SMS * BLOCKS_PER_SM;        // 296, exact-fit one wave

    gap_kernel<<<blocks, THREADS_PER_BLOCK>>>(x, Ww, Wb, out, n_pairs);
}